// round 9
// baseline (speedup 1.0000x reference)
#include <cuda_runtime.h>
#include <cuda_fp16.h>

#define TEXN   1024
#define TT     (TEXN * TEXN)
#define CH     16
#define BB     4
#define HH     768
#define WW     768
#define HW     (HH * WW)
#define NPIX   (BB * HW)

#define CLAMP_LO (-123.68f)
#define CLAMP_HI (151.061f)

// Channel-interleaved clamped texture, fp16 [y][x][c] (33.5 MB, L2-resident).
// +32 halves zero pad: 64B span load at x0==1023 overreads 32B; wx==0 there
// so the zero pad contributes 0*0 (no NaN).
__device__ __half g_tex[TT * CH + 32];

// ---------------------------------------------------------------------------
// Pass 1: clamp + transpose + fp16 convert, [C,T,T] f32 -> [T,T,C] f16.
// ---------------------------------------------------------------------------
__global__ __launch_bounds__(256)
void clamp_transpose_kernel(const float* __restrict__ data) {
    int p4 = (blockIdx.x * blockDim.x + threadIdx.x) * 4;
    if (p4 >= TT) return;

    __half h[4][CH];
#pragma unroll
    for (int c = 0; c < CH; c++) {
        float4 t = __ldcs(reinterpret_cast<const float4*>(&data[c * TT + p4]));
        h[0][c] = __float2half_rn(fminf(fmaxf(t.x, CLAMP_LO), CLAMP_HI));
        h[1][c] = __float2half_rn(fminf(fmaxf(t.y, CLAMP_LO), CLAMP_HI));
        h[2][c] = __float2half_rn(fminf(fmaxf(t.z, CLAMP_LO), CLAMP_HI));
        h[3][c] = __float2half_rn(fminf(fmaxf(t.w, CLAMP_LO), CLAMP_HI));
    }

    uint4* dst = reinterpret_cast<uint4*>(g_tex + (size_t)p4 * CH);
#pragma unroll
    for (int i = 0; i < 4; i++) {
        const uint4* src = reinterpret_cast<const uint4*>(&h[i][0]);
        dst[i * 2 + 0] = src[0];
        dst[i * 2 + 1] = src[1];
    }
}

// ---------------------------------------------------------------------------
// Pass 2: bilinear sample. 4 threads/pixel, 4 PIXELS/THREAD, 256 px/block.
// __launch_bounds__(256, 4) -> 64-reg budget so ALL 8 texture LDG.128 stay
// in flight (R8's reg-32 cap silently serialized them). Addresses computed
// for all pixels first, then all loads issued.
//   Exchange: 2 SHFL.32 per row -> other x-corner for my own 4 channels.
//   Math:    x-lerp half2, y-lerp fp32.
//   Stores:  smem [16][260], XOR-swizzled cols, conflict-free; writeback
//            1KB-contiguous float4 __stcs per channel plane.
// ---------------------------------------------------------------------------
#define NPX_T   4
#define PXB     256
#define SOUT_STRIDE 260           // 256 + 4 pad; 1040B row, 16B aligned

__global__ __launch_bounds__(256, 4)
void sample_kernel(const float2* __restrict__ grid, float* __restrict__ out) {
    __shared__ __align__(16) float s_out[CH * SOUT_STRIDE];

    int tid = threadIdx.x;
    int lp  = tid >> 2;                  // 0..63; handles px lp + 64*i
    int q   = tid & 3;
    int base = blockIdx.x * PXB;         // exact grid; HW % 256 == 0

    const char* tbase = reinterpret_cast<const char*>(g_tex);
    unsigned qoff = (unsigned)q << 4;

    // ---- grid loads (independent) ----
    float2 g[NPX_T];
#pragma unroll
    for (int i = 0; i < NPX_T; i++)
        g[i] = __ldg(&grid[base + lp + 64 * i]);

    // ---- all addresses, then all loads ----
    unsigned a0[NPX_T], a1[NPX_T];
    float wx[NPX_T], wy[NPX_T];
#pragma unroll
    for (int i = 0; i < NPX_T; i++) {
        float ix = fminf(fmaxf(fmaf(g[i].x, 511.5f, 511.5f), 0.0f), 1023.0f);
        float iy = fminf(fmaxf(fmaf(g[i].y, 511.5f, 511.5f), 0.0f), 1023.0f);
        float x0f = floorf(ix), y0f = floorf(iy);
        wx[i] = ix - x0f; wy[i] = iy - y0f;
        int x0 = (int)x0f, y0 = (int)y0f;
        a0[i] = ((unsigned)y0 << 15) + ((unsigned)x0 << 5) + qoff;
        a1[i] = a0[i] + ((y0 < TEXN - 1) ? 32768u : 0u);
    }

    uint4 u0[NPX_T], u1[NPX_T];
#pragma unroll
    for (int i = 0; i < NPX_T; i++) {
        u0[i] = *reinterpret_cast<const uint4*>(tbase + a0[i]);
        u1[i] = *reinterpret_cast<const uint4*>(tbase + a1[i]);
    }

    bool hiX = (q & 2) != 0;
    int ch   = (q & 1) * 8 + (q & 2) * 2;         // 0-3,8-11,4-7,12-15
    int col0 = lp ^ ((q & 1) << 3);               // XOR swizzle, low 6 bits

#pragma unroll
    for (int i = 0; i < NPX_T; i++) {
        unsigned recv0a = __shfl_xor_sync(0xffffffffu, hiX ? u0[i].x : u0[i].z, 2);
        unsigned recv0b = __shfl_xor_sync(0xffffffffu, hiX ? u0[i].y : u0[i].w, 2);
        unsigned recv1a = __shfl_xor_sync(0xffffffffu, hiX ? u1[i].x : u1[i].z, 2);
        unsigned recv1b = __shfl_xor_sync(0xffffffffu, hiX ? u1[i].y : u1[i].w, 2);

        unsigned own0a = hiX ? u0[i].z : u0[i].x;
        unsigned own0b = hiX ? u0[i].w : u0[i].y;
        unsigned own1a = hiX ? u1[i].z : u1[i].x;
        unsigned own1b = hiX ? u1[i].w : u1[i].y;

        float w_own = hiX ? wx[i] : (1.0f - wx[i]);
        __half2 wo2 = __float2half2_rn(w_own);
        __half2 wt2 = __float2half2_rn(1.0f - w_own);

        __half2 r0a = __hfma2(*reinterpret_cast<const __half2*>(&recv0a), wt2,
                      __hmul2(*reinterpret_cast<const __half2*>(&own0a), wo2));
        __half2 r0b = __hfma2(*reinterpret_cast<const __half2*>(&recv0b), wt2,
                      __hmul2(*reinterpret_cast<const __half2*>(&own0b), wo2));
        __half2 r1a = __hfma2(*reinterpret_cast<const __half2*>(&recv1a), wt2,
                      __hmul2(*reinterpret_cast<const __half2*>(&own1a), wo2));
        __half2 r1b = __hfma2(*reinterpret_cast<const __half2*>(&recv1b), wt2,
                      __hmul2(*reinterpret_cast<const __half2*>(&own1b), wo2));

        float2 f0a = __half22float2(r0a);
        float2 f0b = __half22float2(r0b);
        float2 f1a = __half22float2(r1a);
        float2 f1b = __half22float2(r1b);

        float res[4];
        res[0] = f0a.x + (f1a.x - f0a.x) * wy[i];
        res[1] = f0a.y + (f1a.y - f0a.y) * wy[i];
        res[2] = f0b.x + (f1b.x - f0b.x) * wy[i];
        res[3] = f0b.y + (f1b.y - f0b.y) * wy[i];

#pragma unroll
        for (int j = 0; j < 4; j++)
            s_out[(ch + j) * SOUT_STRIDE + col0 + 64 * i] = res[j];
    }

    __syncthreads();

    // Writeback: 4 rounds; idx = tid + 256r -> channel idx>>6, float4 group
    // v = idx&63; un-swizzle group v ^ 2*k(c). 1KB contiguous per plane.
    int b  = base / HW;
    int hw = base - b * HW;              // multiple of 256
#pragma unroll
    for (int r = 0; r < NPX_T; r++) {
        int idx = tid + r * 256;
        int c = idx >> 6;
        int v = idx & 63;
        int vv = v ^ (((c >> 3) & 1) << 1);
        float4 val = *reinterpret_cast<const float4*>(&s_out[c * SOUT_STRIDE + vv * 4]);
        float* o = out + ((size_t)b * CH + c) * HW + hw + v * 4;
        __stcs(reinterpret_cast<float4*>(o), val);
    }
}

extern "C" void kernel_launch(void* const* d_in, const int* in_sizes, int n_in,
                              void* d_out, int out_size) {
    const float* x_grid = (const float*)d_in[0];
    const float* data   = (const float*)d_in[1];
    if (n_in >= 2 && in_sizes[0] == TT * CH) {
        data   = (const float*)d_in[0];
        x_grid = (const float*)d_in[1];
    }

    float* out = (float*)d_out;

    {
        int threads = 256;
        int blocks = (TT / 4 + threads - 1) / threads;  // 1024
        clamp_transpose_kernel<<<blocks, threads>>>(data);
    }
    {
        int blocks = NPIX / PXB;                         // 9216, exact
        sample_kernel<<<blocks, 256>>>((const float2*)x_grid, out);
    }
}

// round 10
// speedup vs baseline: 1.0389x; 1.0389x over previous
#include <cuda_runtime.h>
#include <cuda_fp16.h>

#define TEXN   1024
#define TT     (TEXN * TEXN)
#define CH     16
#define BB     4
#define HH     768
#define WW     768
#define HW     (HH * WW)
#define NPIX   (BB * HW)

#define CLAMP_LO (-123.68f)
#define CLAMP_HI (151.061f)

// Channel-interleaved clamped texture, fp16 [y][x][c] (33.5 MB, L2-resident).
// +32 halves zero pad: 64B span load at x0==1023 overreads 32B; wx==0 there
// so the zero pad contributes 0*0 (no NaN).
__device__ __half g_tex[TT * CH + 32];

// ---------------------------------------------------------------------------
// Pass 1: clamp + transpose + fp16 convert, [C,T,T] f32 -> [T,T,C] f16.
// ---------------------------------------------------------------------------
__global__ __launch_bounds__(256)
void clamp_transpose_kernel(const float* __restrict__ data) {
    int p4 = (blockIdx.x * blockDim.x + threadIdx.x) * 4;
    if (p4 >= TT) return;

    __half h[4][CH];
#pragma unroll
    for (int c = 0; c < CH; c++) {
        float4 t = __ldcs(reinterpret_cast<const float4*>(&data[c * TT + p4]));
        h[0][c] = __float2half_rn(fminf(fmaxf(t.x, CLAMP_LO), CLAMP_HI));
        h[1][c] = __float2half_rn(fminf(fmaxf(t.y, CLAMP_LO), CLAMP_HI));
        h[2][c] = __float2half_rn(fminf(fmaxf(t.z, CLAMP_LO), CLAMP_HI));
        h[3][c] = __float2half_rn(fminf(fmaxf(t.w, CLAMP_LO), CLAMP_HI));
    }

    uint4* dst = reinterpret_cast<uint4*>(g_tex + (size_t)p4 * CH);
#pragma unroll
    for (int i = 0; i < 4; i++) {
        const uint4* src = reinterpret_cast<const uint4*>(&h[i][0]);
        dst[i * 2 + 0] = src[0];
        dst[i * 2 + 1] = src[1];
    }
}

// ---------------------------------------------------------------------------
// Pass 2: bilinear sample. R7 shape (proven fastest): 4 threads/pixel,
// 2 pixels/thread, MLP=4 texture LDG.128 in flight — but 128-THREAD BLOCKS
// (64 px) to halve the __syncthreads convoy width, and __ldcs grid loads to
// keep the texture L2-resident.
//   Loads:   lane q takes the q-th 16B of the 64B (x0,x1) row span.
//   Exchange: 2 SHFL.32 per row -> other x-corner for my own 4 channels.
//   Math:    x-lerp half2, y-lerp fp32.
//   Stores:  smem [16][68], XOR-swizzled cols (conflict-free, same per-warp
//            algebra as R7), writeback 256B-contiguous float4 __stcs.
// ---------------------------------------------------------------------------
#define SOUT_STRIDE 68    // 64 px + 4 pad floats; 272B row, 16B aligned

struct PixIn {
    uint4 u0, u1;         // raw 16B quarters, rows y0/y1
    float wx, wy;
};

__device__ __forceinline__ void load_pix(float2 g, const char* tbase,
                                         unsigned qoff, PixIn& p) {
    float ix = fminf(fmaxf(fmaf(g.x, 511.5f, 511.5f), 0.0f), 1023.0f);
    float iy = fminf(fmaxf(fmaf(g.y, 511.5f, 511.5f), 0.0f), 1023.0f);
    float x0f = floorf(ix), y0f = floorf(iy);
    p.wx = ix - x0f; p.wy = iy - y0f;
    int x0 = (int)x0f, y0 = (int)y0f;
    unsigned r0 = ((unsigned)y0 << 15) + ((unsigned)x0 << 5) + qoff;
    unsigned r1 = r0 + ((y0 < TEXN - 1) ? 32768u : 0u);
    p.u0 = *reinterpret_cast<const uint4*>(tbase + r0);
    p.u1 = *reinterpret_cast<const uint4*>(tbase + r1);
}

__device__ __forceinline__ void compute_pix(const PixIn& p, bool hiX, float* res) {
    unsigned recv0a = __shfl_xor_sync(0xffffffffu, hiX ? p.u0.x : p.u0.z, 2);
    unsigned recv0b = __shfl_xor_sync(0xffffffffu, hiX ? p.u0.y : p.u0.w, 2);
    unsigned recv1a = __shfl_xor_sync(0xffffffffu, hiX ? p.u1.x : p.u1.z, 2);
    unsigned recv1b = __shfl_xor_sync(0xffffffffu, hiX ? p.u1.y : p.u1.w, 2);

    unsigned own0a = hiX ? p.u0.z : p.u0.x;
    unsigned own0b = hiX ? p.u0.w : p.u0.y;
    unsigned own1a = hiX ? p.u1.z : p.u1.x;
    unsigned own1b = hiX ? p.u1.w : p.u1.y;

    float w_own = hiX ? p.wx : (1.0f - p.wx);
    __half2 wo2 = __float2half2_rn(w_own);
    __half2 wt2 = __float2half2_rn(1.0f - w_own);

    __half2 r0a = __hfma2(*reinterpret_cast<const __half2*>(&recv0a), wt2,
                  __hmul2(*reinterpret_cast<const __half2*>(&own0a), wo2));
    __half2 r0b = __hfma2(*reinterpret_cast<const __half2*>(&recv0b), wt2,
                  __hmul2(*reinterpret_cast<const __half2*>(&own0b), wo2));
    __half2 r1a = __hfma2(*reinterpret_cast<const __half2*>(&recv1a), wt2,
                  __hmul2(*reinterpret_cast<const __half2*>(&own1a), wo2));
    __half2 r1b = __hfma2(*reinterpret_cast<const __half2*>(&recv1b), wt2,
                  __hmul2(*reinterpret_cast<const __half2*>(&own1b), wo2));

    float2 f0a = __half22float2(r0a);
    float2 f0b = __half22float2(r0b);
    float2 f1a = __half22float2(r1a);
    float2 f1b = __half22float2(r1b);

    res[0] = f0a.x + (f1a.x - f0a.x) * p.wy;
    res[1] = f0a.y + (f1a.y - f0a.y) * p.wy;
    res[2] = f0b.x + (f1b.x - f0b.x) * p.wy;
    res[3] = f0b.y + (f1b.y - f0b.y) * p.wy;
}

__global__ __launch_bounds__(128)
void sample_kernel(const float2* __restrict__ grid, float* __restrict__ out) {
    __shared__ __align__(16) float s_out[CH * SOUT_STRIDE];

    int tid = threadIdx.x;                // 0..127
    int lp  = tid >> 2;                   // 0..31; handles px lp and lp+32
    int q   = tid & 3;
    int base = blockIdx.x * 64;           // exact grid; HW % 64 == 0

    // ---- issue all loads up front (MLP) ----
    float2 g0 = __ldcs(&grid[base + lp]);
    float2 g1 = __ldcs(&grid[base + lp + 32]);

    const char* tbase = reinterpret_cast<const char*>(g_tex);
    unsigned qoff = (unsigned)q << 4;

    PixIn p0, p1;
    load_pix(g0, tbase, qoff, p0);
    load_pix(g1, tbase, qoff, p1);

    bool hiX = (q & 2) != 0;
    float res0[4], res1[4];
    compute_pix(p0, hiX, res0);
    compute_pix(p1, hiX, res1);

    // lane q's channels: 0-3, 8-11, 4-7, 12-15; XOR-swizzled column.
    // (swizzle XORs bit3 of a 0..31 column index; +32 offset bit untouched)
    int ch   = (q & 1) * 8 + (q & 2) * 2;
    int col0 = lp ^ ((q & 1) << 3);
#pragma unroll
    for (int j = 0; j < 4; j++) {
        s_out[(ch + j) * SOUT_STRIDE + col0]      = res0[j];
        s_out[(ch + j) * SOUT_STRIDE + col0 + 32] = res1[j];
    }

    __syncthreads();

    // Writeback: 2 rounds; idx = tid + 128r -> channel idx>>4, float4 group
    // v = idx&15; un-swizzle group v ^ 2*k(c). 256B contiguous per plane.
    int b  = base / HW;
    int hw = base - b * HW;               // multiple of 64
#pragma unroll
    for (int r = 0; r < 2; r++) {
        int idx = tid + r * 128;
        int c = idx >> 4;                 // 0..15
        int v = idx & 15;                 // 0..15
        int vv = v ^ (((c >> 3) & 1) << 1);
        float4 val = *reinterpret_cast<const float4*>(&s_out[c * SOUT_STRIDE + vv * 4]);
        float* o = out + ((size_t)b * CH + c) * HW + hw + v * 4;
        __stcs(reinterpret_cast<float4*>(o), val);
    }
}

extern "C" void kernel_launch(void* const* d_in, const int* in_sizes, int n_in,
                              void* d_out, int out_size) {
    const float* x_grid = (const float*)d_in[0];
    const float* data   = (const float*)d_in[1];
    if (n_in >= 2 && in_sizes[0] == TT * CH) {
        data   = (const float*)d_in[0];
        x_grid = (const float*)d_in[1];
    }

    float* out = (float*)d_out;

    {
        int threads = 256;
        int blocks = (TT / 4 + threads - 1) / threads;  // 1024
        clamp_transpose_kernel<<<blocks, threads>>>(data);
    }
    {
        int blocks = NPIX / 64;                          // 36864, exact
        sample_kernel<<<blocks, 128>>>((const float2*)x_grid, out);
    }
}

// round 11
// speedup vs baseline: 1.0491x; 1.0098x over previous
#include <cuda_runtime.h>
#include <cuda_fp16.h>

#define TEXN   1024
#define TT     (TEXN * TEXN)
#define CH     16
#define BB     4
#define HH     768
#define WW     768
#define HW     (HH * WW)
#define NPIX   (BB * HW)

#define CLAMP_LO (-123.68f)
#define CLAMP_HI (151.061f)

// Overlapped-block texture layout, fp16:
//   row y = 342 blocks of 128B; block m holds texels 3m..3m+3 (16 ch each,
//   32B per texel). Any bilinear pair (x0,x0+1) lives fully inside block
//   floor(x0/3) at offset (x0-3m)*32 -> the 64B gather span NEVER crosses a
//   128B line (2.0 L1 wavefronts/px instead of 2.5).
//   44.8 MB, L2-resident. Phantom slots (texel index >= 1024 in the last
//   block) are written as zeros every launch; they are only read with
//   bilinear weight exactly 0.
#define NBLK     342                   // ceil(1024/3)
#define RSTRIDE  (NBLK * 128)          // 43776 bytes per row
__device__ __align__(128) __half g_tex[(size_t)TEXN * NBLK * 64];

// ---------------------------------------------------------------------------
// Pass 1: clamp + fp16 + repack into overlapped blocks.
// One thread per (y, block m): 4 texels x 16 ch scalar loads (predicated at
// the row tail), one 128B contiguous store. DRAM-bound (~67MB rd, 44.8MB wr).
// ---------------------------------------------------------------------------
__global__ __launch_bounds__(352)
void clamp_transpose_kernel(const float* __restrict__ data) {
    int m = threadIdx.x;               // 0..351, guard to 342
    int y = blockIdx.x;                // 0..1023
    if (m >= NBLK) return;

    int xbase = 3 * m;
    const float* src = data + (size_t)y * TEXN + xbase;

    __half outh[64];                   // 4 slots x 16 ch (kept in regs)
#pragma unroll
    for (int c = 0; c < CH; c++) {
        const float* sc = src + (size_t)c * TT;
#pragma unroll
        for (int j = 0; j < 4; j++) {
            float v = (xbase + j < TEXN) ? __ldcs(sc + j) : 0.0f;
            v = fminf(fmaxf(v, CLAMP_LO), CLAMP_HI);
            outh[j * 16 + c] = __float2half_rn(v);
        }
    }

    uint4* dst = reinterpret_cast<uint4*>(
        reinterpret_cast<char*>(g_tex) + (size_t)y * RSTRIDE + (size_t)m * 128);
    const uint4* srcw = reinterpret_cast<const uint4*>(outh);
#pragma unroll
    for (int i = 0; i < 8; i++)
        dst[i] = srcw[i];
}

// ---------------------------------------------------------------------------
// Pass 2: bilinear sample (R10 shape: 4 thr/px, 2 px/thread, 128-thr blocks).
//   Loads:   lane q takes the q-th 16B of the line-aligned 64B pair span.
//   Exchange: 2 SHFL.32 per row -> other x-corner for my own 4 channels.
//   Math:    x-lerp half2, y-lerp fp32.
//   Stores:  smem [16][68] XOR-swizzled (conflict-free), 256B-contiguous
//            float4 __stcs writeback.
// ---------------------------------------------------------------------------
#define SOUT_STRIDE 68

struct PixIn {
    uint4 u0, u1;
    float wx, wy;
};

__device__ __forceinline__ void load_pix(float2 g, const char* tbase,
                                         unsigned qoff, PixIn& p) {
    float ix = fminf(fmaxf(fmaf(g.x, 511.5f, 511.5f), 0.0f), 1023.0f);
    float iy = fminf(fmaxf(fmaf(g.y, 511.5f, 511.5f), 0.0f), 1023.0f);
    float x0f = floorf(ix), y0f = floorf(iy);
    p.wx = ix - x0f; p.wy = iy - y0f;
    int x0 = (int)x0f, y0 = (int)y0f;
    unsigned m = ((unsigned)x0 * 43691u) >> 17;     // x0/3 (exact, x0<196K)
    unsigned o = (unsigned)x0 - 3u * m;             // 0..2
    unsigned r0 = (unsigned)y0 * (unsigned)RSTRIDE + (m << 7) + (o << 5) + qoff;
    unsigned r1 = r0 + ((y0 < TEXN - 1) ? (unsigned)RSTRIDE : 0u);
    p.u0 = *reinterpret_cast<const uint4*>(tbase + r0);
    p.u1 = *reinterpret_cast<const uint4*>(tbase + r1);
}

__device__ __forceinline__ void compute_pix(const PixIn& p, bool hiX, float* res) {
    unsigned recv0a = __shfl_xor_sync(0xffffffffu, hiX ? p.u0.x : p.u0.z, 2);
    unsigned recv0b = __shfl_xor_sync(0xffffffffu, hiX ? p.u0.y : p.u0.w, 2);
    unsigned recv1a = __shfl_xor_sync(0xffffffffu, hiX ? p.u1.x : p.u1.z, 2);
    unsigned recv1b = __shfl_xor_sync(0xffffffffu, hiX ? p.u1.y : p.u1.w, 2);

    unsigned own0a = hiX ? p.u0.z : p.u0.x;
    unsigned own0b = hiX ? p.u0.w : p.u0.y;
    unsigned own1a = hiX ? p.u1.z : p.u1.x;
    unsigned own1b = hiX ? p.u1.w : p.u1.y;

    float w_own = hiX ? p.wx : (1.0f - p.wx);
    __half2 wo2 = __float2half2_rn(w_own);
    __half2 wt2 = __float2half2_rn(1.0f - w_own);

    __half2 r0a = __hfma2(*reinterpret_cast<const __half2*>(&recv0a), wt2,
                  __hmul2(*reinterpret_cast<const __half2*>(&own0a), wo2));
    __half2 r0b = __hfma2(*reinterpret_cast<const __half2*>(&recv0b), wt2,
                  __hmul2(*reinterpret_cast<const __half2*>(&own0b), wo2));
    __half2 r1a = __hfma2(*reinterpret_cast<const __half2*>(&recv1a), wt2,
                  __hmul2(*reinterpret_cast<const __half2*>(&own1a), wo2));
    __half2 r1b = __hfma2(*reinterpret_cast<const __half2*>(&recv1b), wt2,
                  __hmul2(*reinterpret_cast<const __half2*>(&own1b), wo2));

    float2 f0a = __half22float2(r0a);
    float2 f0b = __half22float2(r0b);
    float2 f1a = __half22float2(r1a);
    float2 f1b = __half22float2(r1b);

    res[0] = f0a.x + (f1a.x - f0a.x) * p.wy;
    res[1] = f0a.y + (f1a.y - f0a.y) * p.wy;
    res[2] = f0b.x + (f1b.x - f0b.x) * p.wy;
    res[3] = f0b.y + (f1b.y - f0b.y) * p.wy;
}

__global__ __launch_bounds__(128)
void sample_kernel(const float2* __restrict__ grid, float* __restrict__ out) {
    __shared__ __align__(16) float s_out[CH * SOUT_STRIDE];

    int tid = threadIdx.x;
    int lp  = tid >> 2;                   // 0..31; px lp and lp+32
    int q   = tid & 3;
    int base = blockIdx.x * 64;

    float2 g0 = __ldcs(&grid[base + lp]);
    float2 g1 = __ldcs(&grid[base + lp + 32]);

    const char* tbase = reinterpret_cast<const char*>(g_tex);
    unsigned qoff = (unsigned)q << 4;

    PixIn p0, p1;
    load_pix(g0, tbase, qoff, p0);
    load_pix(g1, tbase, qoff, p1);

    bool hiX = (q & 2) != 0;
    float res0[4], res1[4];
    compute_pix(p0, hiX, res0);
    compute_pix(p1, hiX, res1);

    int ch   = (q & 1) * 8 + (q & 2) * 2;  // 0-3,8-11,4-7,12-15
    int col0 = lp ^ ((q & 1) << 3);
#pragma unroll
    for (int j = 0; j < 4; j++) {
        s_out[(ch + j) * SOUT_STRIDE + col0]      = res0[j];
        s_out[(ch + j) * SOUT_STRIDE + col0 + 32] = res1[j];
    }

    __syncthreads();

    int b  = base / HW;
    int hw = base - b * HW;
#pragma unroll
    for (int r = 0; r < 2; r++) {
        int idx = tid + r * 128;
        int c = idx >> 4;
        int v = idx & 15;
        int vv = v ^ (((c >> 3) & 1) << 1);
        float4 val = *reinterpret_cast<const float4*>(&s_out[c * SOUT_STRIDE + vv * 4]);
        float* o = out + ((size_t)b * CH + c) * HW + hw + v * 4;
        __stcs(reinterpret_cast<float4*>(o), val);
    }
}

extern "C" void kernel_launch(void* const* d_in, const int* in_sizes, int n_in,
                              void* d_out, int out_size) {
    const float* x_grid = (const float*)d_in[0];
    const float* data   = (const float*)d_in[1];
    if (n_in >= 2 && in_sizes[0] == TT * CH) {
        data   = (const float*)d_in[0];
        x_grid = (const float*)d_in[1];
    }

    float* out = (float*)d_out;

    clamp_transpose_kernel<<<TEXN, 352>>>(data);           // 1024 blocks
    sample_kernel<<<NPIX / 64, 128>>>((const float2*)x_grid, out);
}